// round 6
// baseline (speedup 1.0000x reference)
#include <cuda_runtime.h>
#include <math.h>

#define NB   512
#define TT   64
#define NLc  32
#define LATc 64
#define HIDc 128
#define G3   384
#define DIN  65
#define MAXG 160

__device__ float g_gix[TT*NB*G3];
__device__ float g_z0 [NB*LATc];
__device__ float g_ys [MAXG*NB*LATc];
__device__ float g_grid[MAXG];
__device__ int   g_niters;
__device__ int   g_mask_mode;
__device__ float g_klrow[NB];
__device__ float g_rpart[4096];
__device__ int   g_ncnt[4096];

__device__ __forceinline__ float mask_at(const void* m, int idx, int mode){
    if (mode==0) return (float)((const unsigned char*)m)[idx];
    if (mode==1) return (float)((const int*)m)[idx];
    return ((const float*)m)[idx];
}

// packed f32x2 helpers (sm_100+)
__device__ __forceinline__ void ffma2(unsigned long long &acc, unsigned long long a, unsigned long long b){
    asm("fma.rn.f32x2 %0, %1, %2, %0;" : "+l"(acc) : "l"(a), "l"(b));
}
__device__ __forceinline__ unsigned long long pack2(float a, float b){
    unsigned long long r; asm("mov.b64 %0, {%1, %2};" : "=l"(r) : "f"(a), "f"(b)); return r;
}
__device__ __forceinline__ float sum2(unsigned long long v){
    float a,b; asm("mov.b64 {%0, %1}, %2;" : "=f"(a), "=f"(b) : "l"(v)); return a+b;
}
__device__ __forceinline__ float tanh_fast(float x){
    float y; asm("tanh.approx.f32 %0, %1;" : "=f"(y) : "f"(x)); return y;
}
__device__ __forceinline__ float sig_fast(float x){ return 0.5f*tanh_fast(0.5f*x) + 0.5f; }

// ---- K0: grid construction (float64, numpy-matching) + mask dtype detect ----
__global__ void k0_grid(const int* __restrict__ tp, const void* __restrict__ msk){
    __shared__ int smn[NB], smx[NB];
    int b = threadIdx.x;
    smn[b] = tp[b*TT];
    smx[b] = tp[b*TT + TT-1];
    __syncthreads();
    if (b == 0){
        int mn = smn[0], mx = smx[0];
        for (int i = 1; i < NB; i++){ mn = min(mn, smn[i]); mx = max(mx, smx[i]); }
        float q0 = (float)mn / 365.0f, q1 = (float)mx / 365.0f;
        double t0 = (double)q0, t1 = (double)q1;
        int n = (int)ceil((t1 - t0)/0.05 + 1.0);
        if (n < 2) n = 2;
        if (n > MAXG) n = MAXG;
        for (int i = 0; i < n; i++){
            double g = (double)i*0.05 + t0;
            if (i == n-1 && g > t1) g = t1;
            g_grid[i] = (float)g;
        }
        g_niters = n;
    }
    if (b == 1){
        const unsigned int* mw = (const unsigned int*)msk;
        bool alli = true, allf = true;
        for (int i = 0; i < 64; i++){
            unsigned v = mw[i];
            if (v != 0u && v != 1u) alli = false;
            if (v != 0u && v != 0x3f800000u) allf = false;
        }
        g_mask_mode = alli ? 1 : (allf ? 2 : 0);
    }
}

// ---- K1: gix[s][b][:] = inp(b, 63-s) @ Wih + bih ----
__global__ void k1_ingemm(const float* __restrict__ obs, const void* __restrict__ msk,
                          const int* __restrict__ tp, const float* __restrict__ Wih,
                          const float* __restrict__ bih){
    extern __shared__ float sm[];
    float* Wsh = sm;              // 65*384
    float* inp = sm + DIN*G3;     // [k][i], 65*64
    int tid = threadIdx.x;        // 384
    int mode = g_mask_mode;
    for (int idx = tid; idx < DIN*G3; idx += G3) Wsh[idx] = Wih[idx];
    int m0 = blockIdx.x * 64;
    for (int idx = tid; idx < DIN*64; idx += G3){
        int k = idx >> 6, i = idx & 63;
        int m = m0 + i; int s = m >> 9; int b = m & 511; int t = TT-1-s;
        int base = (b*TT + t)*NLc;
        float v;
        if (k < NLc)        v = obs[base + k] * mask_at(msk, base + k, mode);
        else if (k < 2*NLc) v = mask_at(msk, base + (k - NLc), mode);
        else                v = (t == 0) ? 0.0f : ((float)tp[b*TT+t] - (float)tp[b*TT+t-1]);
        inp[k*64 + i] = v;
    }
    __syncthreads();
    int j = tid;
    float bj = bih[j];
    for (int i = 0; i < 64; i += 4){
        float a0=bj, a1=bj, a2=bj, a3=bj;
        #pragma unroll 13
        for (int k = 0; k < DIN; k++){
            float w = Wsh[k*G3 + j];
            const float4 iv = *(const float4*)(inp + k*64 + i);
            a0 = fmaf(w, iv.x, a0); a1 = fmaf(w, iv.y, a1);
            a2 = fmaf(w, iv.z, a2); a3 = fmaf(w, iv.w, a3);
        }
        g_gix[(m0+i+0)*G3 + j] = a0;
        g_gix[(m0+i+1)*G3 + j] = a1;
        g_gix[(m0+i+2)*G3 + j] = a2;
        g_gix[(m0+i+3)*G3 + j] = a3;
    }
}

// ---- K2: GRU, 4 batch rows/block, transposed Whh in smem, float4 loads ----
__device__ __forceinline__ void gru_gate(int e, int s, int b0, float* h4, const float* gh4){
    int j = e >> 2, r = e & 3;
    int base = (s*NB + b0 + r)*G3;
    float gr = g_gix[base + j];
    float gz = g_gix[base + HIDc + j];
    float gn = g_gix[base + 2*HIDc + j];
    float rg = sig_fast(gr + gh4[j*4 + r]);
    float zg = sig_fast(gz + gh4[(j+HIDc)*4 + r]);
    float nn = tanh_fast(gn + rg*gh4[(j+2*HIDc)*4 + r]);
    h4[e] = (1.0f - zg)*nn + zg*h4[e];
}

__global__ void __launch_bounds__(384,1) k2_gru(
                       const float* __restrict__ Whh, const float* __restrict__ bhh,
                       const float* __restrict__ Wmu, const float* __restrict__ bmu,
                       const float* __restrict__ Wlv, const float* __restrict__ blv,
                       const float* __restrict__ eps){
    extern __shared__ float sm[];
    float* Wt  = sm;               // 384*132 (transposed, padded)
    float* h4  = sm + 384*132;     // [k][r], 128*4
    float* gh4 = h4 + 512;         // [j][r], 384*4
    int tid = threadIdx.x;         // 384
    int b0 = blockIdx.x * 4;
    for (int k = 0; k < HIDc; k++) Wt[tid*132 + k] = Whh[k*G3 + tid];
    for (int idx = tid; idx < 512; idx += G3) h4[idx] = 0.0f;
    float bj = bhh[tid];
    const float* wp = Wt + tid*132;
    __syncthreads();
    for (int s = 0; s < TT; s++){
        float a0=bj, a1=bj, a2=bj, a3=bj;
        #pragma unroll 8
        for (int k = 0; k < HIDc; k += 4){
            float4 wv = *(const float4*)(wp + k);
            float4 h0 = *(const float4*)(h4 + k*4);
            float4 h1 = *(const float4*)(h4 + k*4 + 4);
            float4 h2 = *(const float4*)(h4 + k*4 + 8);
            float4 h3 = *(const float4*)(h4 + k*4 + 12);
            a0 = fmaf(wv.x,h0.x,a0); a1 = fmaf(wv.x,h0.y,a1); a2 = fmaf(wv.x,h0.z,a2); a3 = fmaf(wv.x,h0.w,a3);
            a0 = fmaf(wv.y,h1.x,a0); a1 = fmaf(wv.y,h1.y,a1); a2 = fmaf(wv.y,h1.z,a2); a3 = fmaf(wv.y,h1.w,a3);
            a0 = fmaf(wv.z,h2.x,a0); a1 = fmaf(wv.z,h2.y,a1); a2 = fmaf(wv.z,h2.z,a2); a3 = fmaf(wv.z,h2.w,a3);
            a0 = fmaf(wv.w,h3.x,a0); a1 = fmaf(wv.w,h3.y,a1); a2 = fmaf(wv.w,h3.z,a2); a3 = fmaf(wv.w,h3.w,a3);
        }
        *(float4*)(gh4 + tid*4) = make_float4(a0,a1,a2,a3);
        __syncthreads();
        gru_gate(tid, s, b0, h4, gh4);
        if (tid < 128) gru_gate(384+tid, s, b0, h4, gh4);
        __syncthreads();
    }
    if (tid < 256){
        int r = tid >> 6, l = tid & 63;
        int b = b0 + r;
        float mu = bmu[l], lv = blv[l];
        #pragma unroll 8
        for (int k = 0; k < HIDc; k++){
            float hv = h4[k*4 + r];
            mu = fmaf(hv, Wmu[k*LATc + l], mu);
            lv = fmaf(hv, Wlv[k*LATc + l], lv);
        }
        g_z0[b*LATc + l] = mu + eps[b*LATc + l]*expf(0.5f*lv);
        gh4[tid] = 1.0f + lv - mu*mu - expf(lv);
    }
    __syncthreads();
    if (tid < 4){
        float sAcc = 0.f;
        for (int l = 0; l < LATc; l++) sAcc += gh4[tid*64 + l];
        g_klrow[b0 + tid] = sAcc;
    }
}

// ---- K3: RK4 latent ODE — 512 threads, packed weight pairs, broadcast state ----
__device__ __forceinline__ void mv4(const unsigned long long* __restrict__ wp,
                                    const float* __restrict__ base, int off, int ng, int st,
                                    float v[4]){
    unsigned long long a0=0ull, a1=0ull, a2=0ull, a3=0ull;
    #pragma unroll
    for (int g = 0; g < 8; g++){
        if (g >= ng) break;
        const float* bp = base + off + g*4;
        ulonglong2 z0 = *(const ulonglong2*)(bp);
        ulonglong2 z1 = *(const ulonglong2*)(bp + st);
        ulonglong2 z2 = *(const ulonglong2*)(bp + 2*st);
        ulonglong2 z3 = *(const ulonglong2*)(bp + 3*st);
        unsigned long long wa = wp[2*g], wb = wp[2*g+1];
        ffma2(a0, wa, z0.x); ffma2(a0, wb, z0.y);
        ffma2(a1, wa, z1.x); ffma2(a1, wb, z1.y);
        ffma2(a2, wa, z2.x); ffma2(a2, wb, z2.y);
        ffma2(a3, wa, z3.x); ffma2(a3, wb, z3.y);
    }
    v[0]=sum2(a0); v[1]=sum2(a1); v[2]=sum2(a2); v[3]=sum2(a3);
}

__global__ void __launch_bounds__(512,1) k3_ode(
                       const float* __restrict__ W1, const float* __restrict__ b1,
                       const float* __restrict__ W2, const float* __restrict__ b2,
                       const float* __restrict__ W3, const float* __restrict__ b3){
    __shared__ float yv[4*68], yt[4*68];        // state row-major [r][64], pad 68
    __shared__ float a1i[4*132], a2i[4*132];    // activations [r][128], pad 132
    __shared__ float pbuf[2048];
    __shared__ float b1s[HIDc], b2s[HIDc], b3s[LATc], gs[MAXG];
    __shared__ int sn;
    int tid = threadIdx.x;                 // 512
    int b0 = blockIdx.x * 4;
    int w = tid >> 5, lane = tid & 31;
    // stage1/2: warp-uniform K-quarter, 32 outputs per warp
    int p12 = w & 3;
    int j12 = (w >> 2)*32 + lane;          // 0..127
    // stage3: warp-uniform K-eighth, 32 outputs per warp-pair
    int s3  = w >> 1;                      // 0..7
    int j3w = (w & 1)*32 + lane;           // 0..63
    // combine mappings
    int cj = tid & 127, cr = tid >> 7;     // stage1/2 combine (j, r)
    int ej = tid & 63,  er = (tid >> 6) & 3; // stage3 combine (j3, r), tid<256

    // packed per-thread weight slices
    unsigned long long w1p[8], w2p[16], w3p[8];
    #pragma unroll
    for (int m = 0; m < 8; m++)
        w1p[m] = pack2(W1[(p12*16 + 2*m)*HIDc + j12], W1[(p12*16 + 2*m + 1)*HIDc + j12]);
    #pragma unroll
    for (int m = 0; m < 16; m++)
        w2p[m] = pack2(W2[(p12*32 + 2*m)*HIDc + j12], W2[(p12*32 + 2*m + 1)*HIDc + j12]);
    #pragma unroll
    for (int m = 0; m < 8; m++)
        w3p[m] = pack2(W3[(s3*16 + 2*m)*LATc + j3w], W3[(s3*16 + 2*m + 1)*LATc + j3w]);

    if (tid < HIDc){ b1s[tid] = b1[tid]; b2s[tid] = b2[tid]; }
    if (tid < LATc) b3s[tid] = b3[tid];
    if (tid < MAXG) gs[tid] = g_grid[tid];
    if (tid == 0) sn = g_niters;
    float yvo = 0.f, ac = 0.f;
    if (tid < 256){
        yvo = g_z0[(b0 + er)*LATc + ej];
        yv[er*68 + ej] = yvo;
        g_ys[(b0 + er)*LATc + ej] = yvo;
    }
    __syncthreads();
    int n = sn;

    for (int i = 0; i < n-1; i++){
        float h = gs[i+1] - gs[i];
        #pragma unroll
        for (int st = 0; st < 4; st++){
            const float* src = (st == 0) ? yv : yt;
            float v[4];
            // stage1: out 128, K=64 quartered
            mv4(w1p, src, p12*16, 4, 68, v);
            #pragma unroll
            for (int r = 0; r < 4; r++) pbuf[p12*512 + r*128 + j12] = v[r];
            __syncthreads();
            {
                float s = pbuf[cr*128 + cj] + pbuf[512 + cr*128 + cj]
                        + pbuf[1024 + cr*128 + cj] + pbuf[1536 + cr*128 + cj];
                a1i[cr*132 + cj] = tanh_fast(s + b1s[cj]);
            }
            __syncthreads();
            // stage2: out 128, K=128 quartered
            mv4(w2p, a1i, p12*32, 8, 132, v);
            #pragma unroll
            for (int r = 0; r < 4; r++) pbuf[p12*512 + r*128 + j12] = v[r];
            __syncthreads();
            {
                float s = pbuf[cr*128 + cj] + pbuf[512 + cr*128 + cj]
                        + pbuf[1024 + cr*128 + cj] + pbuf[1536 + cr*128 + cj];
                a2i[cr*132 + cj] = tanh_fast(s + b2s[cj]);
            }
            __syncthreads();
            // stage3: out 64, K=128 in eighths
            mv4(w3p, a2i, s3*16, 4, 132, v);
            #pragma unroll
            for (int r = 0; r < 4; r++) pbuf[s3*256 + r*64 + j3w] = v[r];
            __syncthreads();
            if (tid < 256){
                float kv = b3s[ej];
                #pragma unroll
                for (int s8 = 0; s8 < 8; s8++) kv += pbuf[s8*256 + er*64 + ej];
                if (st == 0){ ac = kv;          yt[er*68 + ej] = yvo + 0.5f*h*kv; }
                else if (st == 1){ ac += 2.0f*kv; yt[er*68 + ej] = yvo + 0.5f*h*kv; }
                else if (st == 2){ ac += 2.0f*kv; yt[er*68 + ej] = yvo + h*kv; }
                else { yvo += (h/6.0f)*(ac + kv); yv[er*68 + ej] = yvo; }
            }
            __syncthreads();
        }
        if (tid < 256) g_ys[((i+1)*NB + b0 + er)*LATc + ej] = yvo;
    }
}

// ---- K4: interpolate z_bt, decode, masked recon partials ----
__global__ void k4_decode(const float* __restrict__ obs, const void* __restrict__ msk,
                          const int* __restrict__ tp,
                          const float* __restrict__ Wo1, const float* __restrict__ bo1,
                          const float* __restrict__ Wo2, const float* __restrict__ bo2,
                          const int* __restrict__ seq_lens){
    extern __shared__ float sm[];
    float* Wo1s = sm;             // 8192
    float* Wo2s = Wo1s + 8192;    // 4096
    float* bo1s = Wo2s + 4096;    // 128
    float* bo2s = bo1s + 128;     // 32
    float* gs   = bo2s + 32;      // 160
    float* zw   = gs + MAXG;      // 8*64
    float* aw   = zw + 512;       // 8*128
    __shared__ float wsum[8]; __shared__ int wcnt[8];
    int tid = threadIdx.x, w = tid>>5, lane = tid&31;
    for (int i = tid; i < 8192; i += 256) Wo1s[i] = Wo1[i];
    for (int i = tid; i < 4096; i += 256) Wo2s[i] = Wo2[i];
    if (tid < 128) bo1s[tid] = bo1[tid];
    if (tid < 32) bo2s[tid] = bo2[tid];
    if (tid < MAXG) gs[tid] = g_grid[tid];
    __syncthreads();
    int n = g_niters;
    int mode = g_mask_mode;
    int pair = blockIdx.x*8 + w;
    int b = pair >> 6, t = pair & 63;
    float q = (float)tp[b*TT+t] / 365.0f;
    int gi = 0;
    for (int i = 1; i <= n-2; i++) if (gs[i] <= q) gi = i;
    float tl = gs[gi], tr = gs[gi+1];
    float den = (tr-tl==0.f)?1.f:(tr-tl);
    float wq = (q-tl)/den;
    const float* y0 = g_ys + (gi*NB + b)*LATc;
    const float* y1 = g_ys + ((gi+1)*NB + b)*LATc;
    float* z = zw + w*64;
    z[lane]    = y0[lane]*(1.f-wq) + y1[lane]*wq;
    z[lane+32] = y0[lane+32]*(1.f-wq) + y1[lane+32]*wq;
    __syncwarp();
    float* a1 = aw + w*128;
    #pragma unroll
    for (int jj = 0; jj < 4; jj++){
        int jx = lane + jj*32;
        float acc = bo1s[jx];
        #pragma unroll 8
        for (int k = 0; k < 64; k++) acc = fmaf(z[k], Wo1s[k*128+jx], acc);
        a1[jx] = fmaxf(acc, 0.f);
    }
    __syncwarp();
    float acc = bo2s[lane];
    #pragma unroll 8
    for (int k = 0; k < 128; k++) acc = fmaf(a1[k], Wo2s[k*32+lane], acc);
    int valid = (t < seq_lens[b]) ? 1 : 0;
    int base = (b*TT+t)*NLc + lane;
    float mval = mask_at(msk, base, mode) * (float)valid;
    float d = acc - obs[base];
    float sq = mval * d * d;
    int cnt = (mval != 0.f) ? 1 : 0;
    for (int o = 16; o > 0; o >>= 1){
        sq  += __shfl_down_sync(0xffffffffu, sq, o);
        cnt += __shfl_down_sync(0xffffffffu, cnt, o);
    }
    if (lane == 0){ wsum[w] = sq; wcnt[w] = cnt; }
    __syncthreads();
    if (tid == 0){
        float s = 0; int c = 0;
        for (int i = 0; i < 8; i++){ s += wsum[i]; c += wcnt[i]; }
        g_rpart[blockIdx.x] = s; g_ncnt[blockIdx.x] = c;
    }
}

// ---- K5: z_eval + survival head ----
__global__ void k5_eval(const int* __restrict__ tp, const int* __restrict__ seq_lens,
                        const float* __restrict__ age,
                        const float* __restrict__ Ws1, const float* __restrict__ bs1,
                        const float* __restrict__ Ws2, const float* __restrict__ bs2,
                        float* __restrict__ out){
    __shared__ float zs[8*66];
    __shared__ float a1s[8*128];
    __shared__ float gsh[MAXG];
    int tid = threadIdx.x, w = tid>>5, lane = tid&31;
    if (tid < MAXG) gsh[tid] = g_grid[tid];
    __syncthreads();
    int n = g_niters;
    int b = blockIdx.x*8 + w;
    int sl = seq_lens[b];
    float q = (float)tp[b*TT + sl - 1] / 365.0f;
    int gi = 0;
    for (int i = 1; i <= n-2; i++) if (gsh[i] <= q) gi = i;
    float tl = gsh[gi], tr = gsh[gi+1];
    float den = (tr-tl==0.f)?1.f:(tr-tl);
    float wq = (q-tl)/den;
    const float* y0 = g_ys + (gi*NB+b)*LATc;
    const float* y1 = g_ys + ((gi+1)*NB+b)*LATc;
    float* z = zs + w*66;
    float za = y0[lane]*(1.f-wq)+y1[lane]*wq;
    float zb = y0[lane+32]*(1.f-wq)+y1[lane+32]*wq;
    z[lane] = za; z[lane+32] = zb;
    out[1026 + b*64 + lane] = za;
    out[1026 + b*64 + lane + 32] = zb;
    if (lane == 0) z[64] = age[b];
    __syncwarp();
    float* a1 = a1s + w*128;
    #pragma unroll
    for (int jj = 0; jj < 4; jj++){
        int jx = lane + jj*32;
        float acc = bs1[jx];
        for (int k = 0; k < 65; k++) acc = fmaf(z[k], Ws1[k*128+jx], acc);
        a1[jx] = fmaxf(acc, 0.f);
    }
    __syncwarp();
    if (lane < 2){
        float acc = bs2[lane];
        for (int k = 0; k < 128; k++) acc = fmaf(a1[k], Ws2[k*2+lane], acc);
        out[b*2 + lane] = acc;
    }
}

// ---- K6: finalize scalars ----
__global__ void k6_final(float* __restrict__ out){
    __shared__ double sd[256]; __shared__ long long si[256]; __shared__ double kd[256];
    int tid = threadIdx.x;
    double s = 0; long long c = 0;
    for (int i = tid; i < 4096; i += 256){ s += (double)g_rpart[i]; c += g_ncnt[i]; }
    double ks = 0;
    for (int i = tid; i < NB; i += 256) ks += (double)g_klrow[i];
    sd[tid]=s; si[tid]=c; kd[tid]=ks; __syncthreads();
    for (int o=128;o>0;o>>=1){ if(tid<o){ sd[tid]+=sd[tid+o]; si[tid]+=si[tid+o]; kd[tid]+=kd[tid+o]; } __syncthreads(); }
    if (tid==0){
        double nn = (double)si[0];
        out[1024] = (nn > 0.0) ? (float)(sd[0] / (nn > 1.0 ? nn : 1.0)) : 0.f;
        out[1025] = (float)(-0.5 * (kd[0] / (double)NB));
    }
}

extern "C" void kernel_launch(void* const* d_in, const int* in_sizes, int n_in,
                              void* d_out, int out_size) {
    const float* obs = (const float*)d_in[0];
    const float* age = (const float*)d_in[1];
    const float* eps = (const float*)d_in[2];
    const float* Wih = (const float*)d_in[3];
    const float* Whh = (const float*)d_in[4];
    const float* bih = (const float*)d_in[5];
    const float* bhh = (const float*)d_in[6];
    const float* Wmu = (const float*)d_in[7];
    const float* bmu = (const float*)d_in[8];
    const float* Wlv = (const float*)d_in[9];
    const float* blv = (const float*)d_in[10];
    const float* W1  = (const float*)d_in[11];
    const float* b1  = (const float*)d_in[12];
    const float* W2  = (const float*)d_in[13];
    const float* b2  = (const float*)d_in[14];
    const float* W3  = (const float*)d_in[15];
    const float* b3  = (const float*)d_in[16];
    const float* Wo1 = (const float*)d_in[17];
    const float* bo1 = (const float*)d_in[18];
    const float* Wo2 = (const float*)d_in[19];
    const float* bo2 = (const float*)d_in[20];
    const float* Ws1 = (const float*)d_in[21];
    const float* bs1 = (const float*)d_in[22];
    const float* Ws2 = (const float*)d_in[23];
    const float* bs2 = (const float*)d_in[24];
    const void*  msk = d_in[25];
    const int*   tp  = (const int*)d_in[26];
    const int*   sq  = (const int*)d_in[27];
    float* out = (float*)d_out;

    cudaFuncSetAttribute(k1_ingemm, cudaFuncAttributeMaxDynamicSharedMemorySize, 116480);
    cudaFuncSetAttribute(k2_gru,    cudaFuncAttributeMaxDynamicSharedMemorySize, 210944);
    cudaFuncSetAttribute(k4_decode, cudaFuncAttributeMaxDynamicSharedMemorySize, 56576);

    k0_grid<<<1, 512>>>(tp, msk);
    k1_ingemm<<<512, 384, 116480>>>(obs, msk, tp, Wih, bih);
    k2_gru<<<128, 384, 210944>>>(Whh, bhh, Wmu, bmu, Wlv, blv, eps);
    k3_ode<<<128, 512>>>(W1, b1, W2, b2, W3, b3);
    k4_decode<<<4096, 256, 56576>>>(obs, msk, tp, Wo1, bo1, Wo2, bo2, sq);
    k5_eval<<<64, 256>>>(tp, sq, age, Ws1, bs1, Ws2, bs2, out);
    k6_final<<<1, 256>>>(out);
}